// round 4
// baseline (speedup 1.0000x reference)
#include <cuda_runtime.h>
#include <cstdint>
#include <cstddef>

// Problem shape (fixed by reference setup_inputs)
#define B_  256
#define F_  784
#define T_  128
#define U_  2048

#define BT  128   // full T per block
#define BU  64    // u-tile per block
#define BK  8     // k-chunk
#define NKCH (F_ / BK)   // 98

#define ALPHA_  0.9f
#define BETA_   0.85f
#define THRESH_ 1.0f

// Packed dual fp32 FMA (Blackwell f32x2 pipe; only reachable via PTX).
__device__ __forceinline__ void ffma2(float2& c, float2 a, float2 b) {
    asm("fma.rn.f32x2 %0, %1, %2, %0;"
        : "+l"(reinterpret_cast<unsigned long long&>(c))
        : "l"(reinterpret_cast<unsigned long long&>(a)),
          "l"(reinterpret_cast<unsigned long long&>(b)));
}

// One CTA: b = blockIdx.y, u-tile = blockIdx.x*64.
//   Phase 1: h[128 t][64 u] = x[b,:, :]^T (128x784) @ W[:, u0:u0+64]  (fp32 FMA2)
//   Phase 2: per-u scan over t: syn/mem LIF dynamics -> spike writes.
__global__ __launch_bounds__(128, 4)
void snn_fused_kernel(const float* __restrict__ x,
                      const float* __restrict__ W,
                      float* __restrict__ out)
{
    // 8 KB + 8 KB + 32 KB = 48 KB static smem (exactly at the static limit)
    __shared__ float As [2][BK][BT];        // [k][t]
    __shared__ float Bsd[2][BK][2 * BU];    // W values duplicated: [k][u][2]
    __shared__ float Cs [BT][BU];           // h tile for the scan

    const int tid = threadIdx.x;
    const int b   = blockIdx.y;
    const int u0  = blockIdx.x * BU;

    // GEMM micro-tile mapping: 16 (t-groups) x 8 (u-groups), 8x8 per thread
    const int tx = tid & 7;     // u-group: cols tx*8 .. tx*8+7
    const int ty = tid >> 3;    // t-group: rows ty*8 .. ty*8+7

    const float* xb = x + (size_t)b * F_ * T_;   // x[b] is [F][T], t contiguous
    const float* Wb = W + u0;                    // [F][U], u contiguous

    // loaders: 128 threads. As: 8 rows x 128 t (2 float4/thread).
    //          Bsd: 8 rows x 64 u (1 float4/thread, written duplicated).
    const int ka = tid >> 4;            // 0..7
    const int ta = (tid & 15) * 8;      // 0..120
    const int cb = (tid & 15) * 4;      // 0..60

    // accumulators: pairs along t -> acc[i][j] = (C[2i][j], C[2i+1][j]) within micro-tile
    float2 acc[4][8];
#pragma unroll
    for (int i = 0; i < 4; ++i)
#pragma unroll
        for (int j = 0; j < 8; ++j) acc[i][j] = make_float2(0.f, 0.f);

    // ---- prologue: chunk 0 -> buffer 0 ----
    float4 ra0, ra1, rb;
    {
        const float* pa = xb + ka * T_ + ta;
        ra0 = *(const float4*)(pa);
        ra1 = *(const float4*)(pa + 4);
        rb  = *(const float4*)(Wb + ka * U_ + cb);
    }
    *(float4*)&As[0][ka][ta]     = ra0;
    *(float4*)&As[0][ka][ta + 4] = ra1;
    *(float4*)&Bsd[0][ka][2 * cb]     = make_float4(rb.x, rb.x, rb.y, rb.y);
    *(float4*)&Bsd[0][ka][2 * cb + 4] = make_float4(rb.z, rb.z, rb.w, rb.w);
    __syncthreads();

    // ---- main k loop, double buffered ----
    for (int p = 0; p < NKCH; ++p) {
        const int buf = p & 1;
        if (p + 1 < NKCH) {
            const int f0 = (p + 1) * BK;
            const float* pa = xb + (f0 + ka) * T_ + ta;
            ra0 = *(const float4*)(pa);
            ra1 = *(const float4*)(pa + 4);
            rb  = *(const float4*)(Wb + (f0 + ka) * U_ + cb);
        }
#pragma unroll
        for (int kk = 0; kk < BK; ++kk) {
            const float4 av0 = *(const float4*)&As[buf][kk][ty * 8];
            const float4 av1 = *(const float4*)&As[buf][kk][ty * 8 + 4];
            const float4 bv0 = *(const float4*)&Bsd[buf][kk][tx * 16];
            const float4 bv1 = *(const float4*)&Bsd[buf][kk][tx * 16 + 4];
            const float4 bv2 = *(const float4*)&Bsd[buf][kk][tx * 16 + 8];
            const float4 bv3 = *(const float4*)&Bsd[buf][kk][tx * 16 + 12];
            float2 a2[4] = { {av0.x, av0.y}, {av0.z, av0.w},
                             {av1.x, av1.y}, {av1.z, av1.w} };
            float2 bd[8] = { {bv0.x, bv0.y}, {bv0.z, bv0.w},
                             {bv1.x, bv1.y}, {bv1.z, bv1.w},
                             {bv2.x, bv2.y}, {bv2.z, bv2.w},
                             {bv3.x, bv3.y}, {bv3.z, bv3.w} };
#pragma unroll
            for (int i = 0; i < 4; ++i)
#pragma unroll
                for (int j = 0; j < 8; ++j)
                    ffma2(acc[i][j], a2[i], bd[j]);
        }
        if (p + 1 < NKCH) {
            __syncthreads();   // everyone done reading buf^1 (read in iter p-1)
            const int nb = buf ^ 1;
            *(float4*)&As[nb][ka][ta]     = ra0;
            *(float4*)&As[nb][ka][ta + 4] = ra1;
            *(float4*)&Bsd[nb][ka][2 * cb]     = make_float4(rb.x, rb.x, rb.y, rb.y);
            *(float4*)&Bsd[nb][ka][2 * cb + 4] = make_float4(rb.z, rb.z, rb.w, rb.w);
            __syncthreads();   // next-chunk data visible before compute
        }
    }

    // ---- park h tile in smem ----
#pragma unroll
    for (int i = 0; i < 4; ++i) {
        const int t0 = ty * 8 + 2 * i;
        *(float4*)&Cs[t0][tx * 8] =
            make_float4(acc[i][0].x, acc[i][1].x, acc[i][2].x, acc[i][3].x);
        *(float4*)&Cs[t0][tx * 8 + 4] =
            make_float4(acc[i][4].x, acc[i][5].x, acc[i][6].x, acc[i][7].x);
        *(float4*)&Cs[t0 + 1][tx * 8] =
            make_float4(acc[i][0].y, acc[i][1].y, acc[i][2].y, acc[i][3].y);
        *(float4*)&Cs[t0 + 1][tx * 8 + 4] =
            make_float4(acc[i][4].y, acc[i][5].y, acc[i][6].y, acc[i][7].y);
    }
    __syncthreads();

    // ---- LIF scan over t (sequential); one thread per u column ----
    if (tid < BU) {
        float* op = out + (size_t)b * T_ * U_ + u0 + tid;
        float syn = 0.f, mem = 0.f;
#pragma unroll 4
        for (int t = 0; t < T_; ++t) {
            const float h = Cs[t][tid];
            syn = ALPHA_ * syn + h;           // synaptic current decay
            mem = BETA_  * mem + syn;         // membrane decay
            const float v   = mem - THRESH_;
            const float spk = (v > 0.f) ? 1.f : 0.f;  // hard threshold
            mem -= spk * THRESH_;             // soft reset
            op[(size_t)t * U_] = spk;
        }
    }
}

extern "C" void kernel_launch(void* const* d_in, const int* in_sizes, int n_in,
                              void* d_out, int out_size) {
    (void)in_sizes; (void)n_in; (void)out_size;
    const float* x = (const float*)d_in[0];   // [B, F, T] = [256, 784, 128]
    const float* W = (const float*)d_in[1];   // [F, U]    = [784, 2048]
    float* out = (float*)d_out;               // [B, T, U] float32

    dim3 grid(U_ / BU, B_);   // 32 x 256 = 8192 blocks
    snn_fused_kernel<<<grid, 128>>>(x, W, out);
}

// round 6
// speedup vs baseline: 3.4878x; 3.4878x over previous
#include <cuda_runtime.h>
#include <cstdint>
#include <cstddef>

// Problem shape (fixed by reference setup_inputs)
#define B_  256
#define F_  784
#define T_  128
#define U_  2048

#define BT  128   // full T per block
#define BU  64    // u-tile per block
#define BK  8     // k-chunk
#define NKCH (F_ / BK)   // 98

#define ALPHA_  0.9f
#define BETA_   0.85f
#define THRESH_ 1.0f

// Packed dual fp32 FMA (Blackwell f32x2 pipe; only reachable via PTX).
__device__ __forceinline__ void ffma2(float2& c, float2 a, float2 b) {
    asm("fma.rn.f32x2 %0, %1, %2, %0;"
        : "+l"(reinterpret_cast<unsigned long long&>(c))
        : "l"(reinterpret_cast<unsigned long long&>(a)),
          "l"(reinterpret_cast<unsigned long long&>(b)));
}

// Duplicate one fp32 value into both halves of a 64-bit pair (1 MOV-pack).
__device__ __forceinline__ float2 dup2(float v) {
    float2 r;
    asm("mov.b64 %0, {%1, %1};"
        : "=l"(reinterpret_cast<unsigned long long&>(r)) : "f"(v));
    return r;
}

// One CTA: b = blockIdx.y, u-tile = blockIdx.x*64.
//   Phase 1: h[128 t][64 u] = x[b]^T (128x784) @ W[:, u0:u0+64]  (fp32 FFMA2)
//   Phase 2: per-u LIF scan over t -> spike writes.
__global__ __launch_bounds__(128, 4)
void snn_fused_kernel(const float* __restrict__ x,
                      const float* __restrict__ W,
                      float* __restrict__ out)
{
    // 8 KB + 4 KB + 32 KB = 44 KB static smem
    __shared__ float As[2][BK][BT];   // x chunk: [k][t]
    __shared__ float Bs[2][BK][BU];   // W chunk: [k][u]   (NO duplication)
    __shared__ float Cs[BT][BU];      // h tile for the scan

    const int tid = threadIdx.x;
    const int b   = blockIdx.y;
    const int u0  = blockIdx.x * BU;

    // micro-tile mapping: 16 t-groups x 8 u-groups; per thread 8t x 8u.
    // u values are SPLIT:  group0 = tx*4..+3 , group1 = 32+tx*4..+3
    // -> each B LDS.128 has warp lanes at tx*16B: 128 contiguous bytes,
    //    all 32 banks hit exactly once => conflict-free.
    const int tx = tid & 7;     // u-group
    const int ty = tid >> 3;    // t-group: rows ty*8 .. ty*8+7

    const float* xb = x + (size_t)b * F_ * T_;   // x[b] is [F][T], t contiguous
    const float* Wb = W + u0;                    // [F][U], u contiguous

    // loaders: As: 8 rows x 128 t (2 float4/thread). Bs: 8 rows x 64 u (1 float4/thread).
    const int ka = tid >> 4;            // 0..7
    const int ta = (tid & 15) * 8;      // 0..120
    const int cb = (tid & 15) * 4;      // 0..60

    // acc[i][j]: t-pair (ty*8+2i, ty*8+2i+1), u = (j<4) ? tx*4+j : 32+tx*4+j-4
    float2 acc[4][8];
#pragma unroll
    for (int i = 0; i < 4; ++i)
#pragma unroll
        for (int j = 0; j < 8; ++j) acc[i][j] = make_float2(0.f, 0.f);

    // ---- prologue: chunk 0 -> buffer 0 ----
    float4 ra0, ra1, rb;
    {
        const float* pa = xb + ka * T_ + ta;
        ra0 = *(const float4*)(pa);
        ra1 = *(const float4*)(pa + 4);
        rb  = *(const float4*)(Wb + ka * U_ + cb);
    }
    *(float4*)&As[0][ka][ta]     = ra0;
    *(float4*)&As[0][ka][ta + 4] = ra1;
    *(float4*)&Bs[0][ka][cb]     = rb;
    __syncthreads();

    // ---- main k loop, double buffered ----
    for (int p = 0; p < NKCH; ++p) {
        const int buf = p & 1;
        if (p + 1 < NKCH) {
            const int f0 = (p + 1) * BK;
            const float* pa = xb + (f0 + ka) * T_ + ta;
            ra0 = *(const float4*)(pa);
            ra1 = *(const float4*)(pa + 4);
            rb  = *(const float4*)(Wb + (f0 + ka) * U_ + cb);
        }
#pragma unroll
        for (int kk = 0; kk < BK; ++kk) {
            // A: natural t-pairs (conflict-free: 4 distinct 16B lines, broadcast)
            const float4 av0 = *(const float4*)&As[buf][kk][ty * 8];
            const float4 av1 = *(const float4*)&As[buf][kk][ty * 8 + 4];
            // B: split-4 groups, conflict-free LDS.128
            const float4 b0 = *(const float4*)&Bs[buf][kk][tx * 4];
            const float4 b1 = *(const float4*)&Bs[buf][kk][32 + tx * 4];

            float2 a2[4] = { {av0.x, av0.y}, {av0.z, av0.w},
                             {av1.x, av1.y}, {av1.z, av1.w} };
            float2 bd[8] = { dup2(b0.x), dup2(b0.y), dup2(b0.z), dup2(b0.w),
                             dup2(b1.x), dup2(b1.y), dup2(b1.z), dup2(b1.w) };
#pragma unroll
            for (int i = 0; i < 4; ++i)
#pragma unroll
                for (int j = 0; j < 8; ++j)
                    ffma2(acc[i][j], a2[i], bd[j]);
        }
        if (p + 1 < NKCH) {
            __syncthreads();   // everyone done reading buf^1 (read in iter p-1)
            const int nb = buf ^ 1;
            *(float4*)&As[nb][ka][ta]     = ra0;
            *(float4*)&As[nb][ka][ta + 4] = ra1;
            *(float4*)&Bs[nb][ka][cb]     = rb;
            __syncthreads();   // next-chunk data visible before compute
        }
    }

    // ---- park h tile in smem (two float4 groups per t-row) ----
#pragma unroll
    for (int i = 0; i < 4; ++i) {
        const int t0 = ty * 8 + 2 * i;
        *(float4*)&Cs[t0][tx * 4] =
            make_float4(acc[i][0].x, acc[i][1].x, acc[i][2].x, acc[i][3].x);
        *(float4*)&Cs[t0][32 + tx * 4] =
            make_float4(acc[i][4].x, acc[i][5].x, acc[i][6].x, acc[i][7].x);
        *(float4*)&Cs[t0 + 1][tx * 4] =
            make_float4(acc[i][0].y, acc[i][1].y, acc[i][2].y, acc[i][3].y);
        *(float4*)&Cs[t0 + 1][32 + tx * 4] =
            make_float4(acc[i][4].y, acc[i][5].y, acc[i][6].y, acc[i][7].y);
    }
    __syncthreads();

    // ---- LIF scan over t (sequential); one thread per u column ----
    if (tid < BU) {
        float* op = out + (size_t)b * T_ * U_ + u0 + tid;
        float syn = 0.f, mem = 0.f;
#pragma unroll 4
        for (int t = 0; t < T_; ++t) {
            const float h = Cs[t][tid];
            syn = ALPHA_ * syn + h;           // synaptic current decay
            mem = BETA_  * mem + syn;         // membrane decay
            const float v   = mem - THRESH_;
            const float spk = (v > 0.f) ? 1.f : 0.f;  // hard threshold
            mem -= spk * THRESH_;             // soft reset
            op[(size_t)t * U_] = spk;
        }
    }
}

extern "C" void kernel_launch(void* const* d_in, const int* in_sizes, int n_in,
                              void* d_out, int out_size) {
    (void)in_sizes; (void)n_in; (void)out_size;
    const float* x = (const float*)d_in[0];   // [B, F, T] = [256, 784, 128]
    const float* W = (const float*)d_in[1];   // [F, U]    = [784, 2048]
    float* out = (float*)d_out;               // [B, T, U] float32

    dim3 grid(U_ / BU, B_);   // 32 x 256 = 8192 blocks
    snn_fused_kernel<<<grid, 128>>>(x, W, out);
}

// round 7
// speedup vs baseline: 3.6736x; 1.0533x over previous
#include <cuda_runtime.h>
#include <cstdint>
#include <cstddef>

// Problem shape (fixed by reference setup_inputs)
#define B_  256
#define F_  784
#define T_  128
#define U_  2048

#define BT  128            // full T per block
#define BU  64             // u-tile per block
#define BK  16             // k-chunk
#define NKCH (F_ / BK)     // 49

#define ALPHA_  0.9f
#define BETA_   0.85f
#define THRESH_ 1.0f

// Packed dual fp32 FMA (Blackwell f32x2 pipe; only reachable via PTX).
__device__ __forceinline__ void ffma2(float2& c, float2 a, float2 b) {
    asm("fma.rn.f32x2 %0, %1, %2, %0;"
        : "+l"(reinterpret_cast<unsigned long long&>(c))
        : "l"(reinterpret_cast<unsigned long long&>(a)),
          "l"(reinterpret_cast<unsigned long long&>(b)));
}

// Duplicate one fp32 value into both halves of a 64-bit pair (1 MOV-pack, ALU pipe).
__device__ __forceinline__ float2 dup2(float v) {
    float2 r;
    asm("mov.b64 %0, {%1, %1};"
        : "=l"(reinterpret_cast<unsigned long long&>(r)) : "f"(v));
    return r;
}

// 16-byte async global->shared copy (LDGSTS), L1-bypass.
__device__ __forceinline__ void cp_async16(uint32_t smem_addr, const void* gptr) {
    asm volatile("cp.async.cg.shared.global [%0], [%1], 16;"
                 :: "r"(smem_addr), "l"(gptr) : "memory");
}
__device__ __forceinline__ void cp_commit() {
    asm volatile("cp.async.commit_group;" ::: "memory");
}
__device__ __forceinline__ void cp_wait0() {
    asm volatile("cp.async.wait_group 0;" ::: "memory");
}

// One CTA: b = blockIdx.y, u-tile = blockIdx.x*64.
//   Phase 1: h[128 t][64 u] = x[b]^T (128x784) @ W[:, u0:u0+64]  (fp32 FFMA2)
//   Phase 2: per-u LIF scan over t -> spike writes.
__global__ __launch_bounds__(128, 4)
void snn_fused_kernel(const float* __restrict__ x,
                      const float* __restrict__ W,
                      float* __restrict__ out)
{
    // Aliased smem: mainloop uses As(16KB)+Bs(8KB); epilogue reuses the same
    // bytes as Cs(32KB). Total static smem = 32 KB.
    __shared__ __align__(16) char sraw[BT * BU * 4];   // 32768 bytes
    float (*As)[BK][BT] = reinterpret_cast<float (*)[BK][BT]>(sraw);           // [2][16][128]
    float (*Bs)[BK][BU] = reinterpret_cast<float (*)[BK][BU]>(sraw + 2 * BK * BT * 4); // [2][16][64]
    float (*Cs)[BU]     = reinterpret_cast<float (*)[BU]>(sraw);               // [128][64]

    const int tid = threadIdx.x;
    const int b   = blockIdx.y;
    const int u0  = blockIdx.x * BU;

    // micro-tile mapping: 16 t-groups x 8 u-groups; per thread 8t x 8u.
    // u values SPLIT: group0 = tx*4..+3, group1 = 32+tx*4..+3 -> each B LDS.128
    // covers 128 contiguous bytes per half-warp => conflict-free.
    const int tx = tid & 7;     // u-group
    const int ty = tid >> 3;    // t-group: rows ty*8 .. ty*8+7

    const float* xb = x + (size_t)b * F_ * T_;   // x[b] is [F][T], t contiguous
    const float* Wb = W + u0;                    // [F][U], u contiguous

    // cp.async loader mapping (BK=16):
    //   As: 16 rows x 128 t -> 4x16B per thread. ka = tid>>3 (row), ta = (tid&7)*16
    //   Bs: 16 rows x 64 u  -> 2x16B per thread. kb = tid>>3 (row), cbb = (tid&7)*8
    const int ka  = tid >> 3;          // 0..15
    const int ta  = (tid & 7) * 16;    // 0..112
    const int cbb = (tid & 7) * 8;     // 0..56

    // acc[i][j]: t-pair (ty*8+2i, ty*8+2i+1), u = (j<4) ? tx*4+j : 32+tx*4+(j-4)
    float2 acc[4][8];
#pragma unroll
    for (int i = 0; i < 4; ++i)
#pragma unroll
        for (int j = 0; j < 8; ++j) acc[i][j] = make_float2(0.f, 0.f);

    // ---- prologue: chunk 0 -> buffer 0 ----
    {
        const float* pa = xb + ka * T_ + ta;
        uint32_t sA = (uint32_t)__cvta_generic_to_shared(&As[0][ka][ta]);
#pragma unroll
        for (int i = 0; i < 4; ++i) cp_async16(sA + 16 * i, pa + 4 * i);
        const float* pb = Wb + ka * U_ + cbb;
        uint32_t sB = (uint32_t)__cvta_generic_to_shared(&Bs[0][ka][cbb]);
        cp_async16(sB, pb);
        cp_async16(sB + 16, pb + 4);
        cp_commit();
        cp_wait0();
    }
    __syncthreads();

    // ---- main k loop, double buffered, ONE sync per iteration ----
    for (int p = 0; p < NKCH; ++p) {
        const int buf = p & 1;

        // Issue async loads for chunk p+1 into buf^1. Safe: all reads of
        // buf^1 (iteration p-1's compute) completed before the barrier at
        // the end of iteration p-1.
        if (p + 1 < NKCH) {
            const int f0 = (p + 1) * BK;
            const int nb = buf ^ 1;
            const float* pa = xb + (size_t)(f0 + ka) * T_ + ta;
            uint32_t sA = (uint32_t)__cvta_generic_to_shared(&As[nb][ka][ta]);
#pragma unroll
            for (int i = 0; i < 4; ++i) cp_async16(sA + 16 * i, pa + 4 * i);
            const float* pb = Wb + (size_t)(f0 + ka) * U_ + cbb;
            uint32_t sB = (uint32_t)__cvta_generic_to_shared(&Bs[nb][ka][cbb]);
            cp_async16(sB, pb);
            cp_async16(sB + 16, pb + 4);
            cp_commit();
        }

#pragma unroll
        for (int kk = 0; kk < BK; ++kk) {
            // A: natural t-pairs (broadcast, conflict-free)
            const float4 av0 = *(const float4*)&As[buf][kk][ty * 8];
            const float4 av1 = *(const float4*)&As[buf][kk][ty * 8 + 4];
            // B: split-4 groups, conflict-free LDS.128
            const float4 b0 = *(const float4*)&Bs[buf][kk][tx * 4];
            const float4 b1 = *(const float4*)&Bs[buf][kk][32 + tx * 4];

            float2 a2[4] = { {av0.x, av0.y}, {av0.z, av0.w},
                             {av1.x, av1.y}, {av1.z, av1.w} };
            float2 bd[8] = { dup2(b0.x), dup2(b0.y), dup2(b0.z), dup2(b0.w),
                             dup2(b1.x), dup2(b1.y), dup2(b1.z), dup2(b1.w) };
#pragma unroll
            for (int i = 0; i < 4; ++i)
#pragma unroll
                for (int j = 0; j < 8; ++j)
                    ffma2(acc[i][j], a2[i], bd[j]);
        }

        if (p + 1 < NKCH) {
            cp_wait0();        // my chunk-(p+1) slices landed
            __syncthreads();   // everyone's landed; everyone done reading buf
        }
    }

    // ---- park h tile in smem (Cs aliases As/Bs: barrier first) ----
    __syncthreads();
#pragma unroll
    for (int i = 0; i < 4; ++i) {
        const int t0 = ty * 8 + 2 * i;
        *(float4*)&Cs[t0][tx * 4] =
            make_float4(acc[i][0].x, acc[i][1].x, acc[i][2].x, acc[i][3].x);
        *(float4*)&Cs[t0][32 + tx * 4] =
            make_float4(acc[i][4].x, acc[i][5].x, acc[i][6].x, acc[i][7].x);
        *(float4*)&Cs[t0 + 1][tx * 4] =
            make_float4(acc[i][0].y, acc[i][1].y, acc[i][2].y, acc[i][3].y);
        *(float4*)&Cs[t0 + 1][32 + tx * 4] =
            make_float4(acc[i][4].y, acc[i][5].y, acc[i][6].y, acc[i][7].y);
    }
    __syncthreads();

    // ---- LIF scan over t (sequential); one thread per u column ----
    if (tid < BU) {
        float* op = out + (size_t)b * T_ * U_ + u0 + tid;
        float syn = 0.f, mem = 0.f;
#pragma unroll 4
        for (int t = 0; t < T_; ++t) {
            const float h = Cs[t][tid];
            syn = ALPHA_ * syn + h;           // synaptic current decay
            mem = BETA_  * mem + syn;         // membrane decay
            const float v   = mem - THRESH_;
            const float spk = (v > 0.f) ? 1.f : 0.f;  // hard threshold
            mem -= spk * THRESH_;             // soft reset
            op[(size_t)t * U_] = spk;
        }
    }
}

extern "C" void kernel_launch(void* const* d_in, const int* in_sizes, int n_in,
                              void* d_out, int out_size) {
    (void)in_sizes; (void)n_in; (void)out_size;
    const float* x = (const float*)d_in[0];   // [B, F, T] = [256, 784, 128]
    const float* W = (const float*)d_in[1];   // [F, U]    = [784, 2048]
    float* out = (float*)d_out;               // [B, T, U] float32

    dim3 grid(U_ / BU, B_);   // 32 x 256 = 8192 blocks
    snn_fused_kernel<<<grid, 128>>>(x, W, out);
}

// round 10
// speedup vs baseline: 5.3398x; 1.4535x over previous
#include <cuda_runtime.h>
#include <cuda_fp16.h>
#include <cstdint>
#include <cstddef>

// ---------------- problem shape ----------------
#define B_  256
#define F_  784
#define T_  128
#define U_  2048
#define KP  800            // K padded to 25*32
#define KC  32             // k per chunk
#define NCH 25             // KP/KC
#define NT  128            // u-tile per CTA

#define ALPHA_  0.9f
#define BETA_   0.85f
#define THRESH_ 1.0f
#define SPLIT_SCALE 2048.0f
#define INV_SCALE (1.0f / 2048.0f)

// smem stage: 4 arrays (A0,A1,B0,B1) of [128 rows][40 halfs] (32 data + 8 pad)
// row stride 80B -> ldmatrix 16B-groups hit distinct bank phases (5i mod 8).
#define ROWH    40
#define ARR_B   (128 * ROWH * 2)      // 10240
#define STAGE_B (4 * ARR_B)           // 40960
#define SMEM_TOTAL (2 * STAGE_B)      // 81920 (epilogue Cs 128*132*4=67584 aliases)

// ---------------- scratch (device globals; allocation-free rule) ----------
__device__ __half X0d[B_][T_][KP];    // 52.4 MB  main split of x, K-major
__device__ __half X1d[B_][T_][KP];    // 52.4 MB  residual*2048
__device__ __half W0d[U_][KP];        // 3.3 MB
__device__ __half W1d[U_][KP];        // 3.3 MB

// ---------------- PTX helpers (all baseline sm_80 ISA -> compute_103 OK) ---
__device__ __forceinline__ void cp_async16(uint32_t saddr, const void* g) {
    asm volatile("cp.async.cg.shared.global [%0], [%1], 16;"
                 :: "r"(saddr), "l"(g) : "memory");
}
__device__ __forceinline__ void cp_commit() {
    asm volatile("cp.async.commit_group;" ::: "memory");
}
__device__ __forceinline__ void cp_wait1() {
    asm volatile("cp.async.wait_group 1;" ::: "memory");
}
__device__ __forceinline__ void cp_wait0() {
    asm volatile("cp.async.wait_group 0;" ::: "memory");
}
// plain (non-trans) ldmatrix x4: lane l gets M[l/4][2*(l%4)..+1] per 8x8 mat.
__device__ __forceinline__ void ldsm4(uint32_t* r, uint32_t addr) {
    asm volatile("ldmatrix.sync.aligned.m8n8.x4.shared.b16 {%0,%1,%2,%3}, [%4];"
                 : "=r"(r[0]), "=r"(r[1]), "=r"(r[2]), "=r"(r[3]) : "r"(addr));
}
__device__ __forceinline__ void mma16816(float* c, const uint32_t* a, const uint32_t* b) {
    asm volatile(
        "mma.sync.aligned.m16n8k16.row.col.f32.f16.f16.f32 "
        "{%0,%1,%2,%3}, {%4,%5,%6,%7}, {%8,%9}, {%0,%1,%2,%3};"
        : "+f"(c[0]), "+f"(c[1]), "+f"(c[2]), "+f"(c[3])
        : "r"(a[0]), "r"(a[1]), "r"(a[2]), "r"(a[3]), "r"(b[0]), "r"(b[1]));
}
// packed fp16x2 multiply (exact for power-of-two scales; results stay normal)
__device__ __forceinline__ uint32_t hmul2(uint32_t a, uint32_t s) {
    uint32_t d;
    asm("mul.f16x2 %0, %1, %2;" : "=r"(d) : "r"(a), "r"(s));
    return d;
}
#define SCALE_A_2M5 0x28002800u   // half2(2^-5, 2^-5)
#define SCALE_B_2M6 0x24002400u   // half2(2^-6, 2^-6)
__device__ __forceinline__ uint32_t s2u(const void* p) {
    return (uint32_t)__cvta_generic_to_shared(p);
}

// ---------------- split precompute ----------------
// x[b][f][t] -> X0/X1 [b][t][f] (transpose), exact fp16 2-split, zero-pad f>=784.
__global__ void split_x_kernel(const float* __restrict__ x) {
    __shared__ float tile[32][33];
    const int b  = blockIdx.z;
    const int f0 = blockIdx.x * 32;
    const int t0 = blockIdx.y * 32;
    const int tx = threadIdx.x, ty = threadIdx.y;
    for (int i = ty; i < 32; i += 8) {
        const int f = f0 + i;
        float v = 0.f;
        if (f < F_) v = x[((size_t)b * F_ + f) * T_ + t0 + tx];
        tile[i][tx] = v;
    }
    __syncthreads();
    for (int i = ty; i < 32; i += 8) {
        const int t = t0 + i;
        const int f = f0 + tx;
        const float v = tile[tx][i];
        const __half h0 = __float2half_rn(v);
        const float r = v - __half2float(h0);
        const __half h1 = __float2half_rn(r * SPLIT_SCALE);
        X0d[b][t][f] = h0;
        X1d[b][t][f] = h1;
    }
}
// W[f][u] -> W0/W1 [u][f] (K-major)
__global__ void split_w_kernel(const float* __restrict__ W) {
    __shared__ float tile[32][33];
    const int f0 = blockIdx.x * 32;
    const int u0 = blockIdx.y * 32;
    const int tx = threadIdx.x, ty = threadIdx.y;
    for (int i = ty; i < 32; i += 8) {
        const int f = f0 + i;
        float v = 0.f;
        if (f < F_) v = W[(size_t)f * U_ + u0 + tx];
        tile[i][tx] = v;
    }
    __syncthreads();
    for (int i = ty; i < 32; i += 8) {
        const int u = u0 + i;
        const int f = f0 + tx;
        const float v = tile[tx][i];
        const __half h0 = __float2half_rn(v);
        const float r = v - __half2float(h0);
        const __half h1 = __float2half_rn(r * SPLIT_SCALE);
        W0d[u][f] = h0;
        W1d[u][f] = h1;
    }
}

// ---------------- chunk loader: 8 cp.async16 per thread ----------------
__device__ __forceinline__ void load_chunk(uint32_t sb, int stage, int p,
                                           int b, int u0, int tid) {
    const uint32_t st = sb + stage * STAGE_B;
    const int k0 = p * KC;
    const __half* src[4] = { &X0d[b][0][k0], &X1d[b][0][k0],
                             &W0d[u0][k0],  &W1d[u0][k0] };
#pragma unroll
    for (int arr = 0; arr < 4; ++arr) {
#pragma unroll
        for (int i = 0; i < 2; ++i) {
            const int u_  = tid + 256 * i;       // 0..511
            const int row = u_ >> 2;             // 0..127
            const int c16 = u_ & 3;              // 16B unit within 64B row data
            cp_async16(st + arr * ARR_B + row * (ROWH * 2) + c16 * 16,
                       (const char*)src[arr] + (size_t)row * (KP * 2) + c16 * 16);
        }
    }
}

// ---------------- fused mma.sync GEMM + LIF scan ----------------
// Full-precision split product: h = a0b0 + (a0b1 + a1b0 + (a1*2^-5)(b1*2^-6))/2048
// (a1,b1 carry x2048; the rescaled a1m*b1m product carries exactly x2048.)
__global__ __launch_bounds__(256, 1)
void snn_mma_kernel(float* __restrict__ out)
{
    extern __shared__ __align__(128) char smem[];
    const uint32_t sb = s2u(smem);
    const int tid = threadIdx.x;
    const int wid = tid >> 5;
    const int lid = tid & 31;
    const int u0  = blockIdx.x * NT;
    const int b   = blockIdx.y;
    const int m0  = wid * 16;                 // this warp's t rows

    // accumulators: 16 n-tiles x 4 regs, two sets (main, x2048 correction)
    float acc0[64], acc1[64];
#pragma unroll
    for (int i = 0; i < 64; ++i) { acc0[i] = 0.f; acc1[i] = 0.f; }

    // ldmatrix source addresses (lane-dependent row/col-half)
    const int ar = m0 + (lid & 15);           // A rows m0..m0+15
    const int ac = (lid >> 4) & 1;            // k col-half (0:k0-7, 1:k8-15)
    const int brbase = (lid & 7) + ((lid & 16) ? 8 : 0);   // B row within n-pair
    const int bc = (lid >> 3) & 1;

    load_chunk(sb, 0, 0, b, u0, tid);
    cp_commit();

    for (int p = 0; p < NCH; ++p) {
        const int s = p & 1;
        if (p + 1 < NCH) { load_chunk(sb, s ^ 1, p + 1, b, u0, tid); cp_commit(); }
        if (p + 1 < NCH) cp_wait1(); else cp_wait0();   // chunk p landed (mine)
        __syncthreads();                                 // everyone's landed

        const uint32_t st = sb + s * STAGE_B;
#pragma unroll
        for (int ks = 0; ks < 2; ++ks) {                 // two k16 steps
            uint32_t a0f[4], a1f[4], a1m[4];
            const uint32_t aoff = st + ar * (ROWH * 2) + ks * 32 + ac * 16;
            ldsm4(a0f, aoff);                            // A0
            ldsm4(a1f, aoff + ARR_B);                    // A1 (residual*2048)
#pragma unroll
            for (int i = 0; i < 4; ++i) a1m[i] = hmul2(a1f[i], SCALE_A_2M5);
#pragma unroll
            for (int j = 0; j < 8; ++j) {                // n-pairs (16 u each)
                uint32_t b0f[4], b1f[4], b1m[4];
                const uint32_t boff = st + 2 * ARR_B
                    + (j * 16 + brbase) * (ROWH * 2) + ks * 32 + bc * 16;
                ldsm4(b0f, boff);                        // W0
                ldsm4(b1f, boff + ARR_B);                // W1 (residual*2048)
#pragma unroll
                for (int i = 0; i < 4; ++i) b1m[i] = hmul2(b1f[i], SCALE_B_2M6);
                // n-tile 2j   (frag regs [0],[1])
                mma16816(acc0 + (2 * j) * 4,     a0f, b0f);
                mma16816(acc1 + (2 * j) * 4,     a0f, b1f);
                mma16816(acc1 + (2 * j) * 4,     a1f, b0f);
                mma16816(acc1 + (2 * j) * 4,     a1m, b1m);
                // n-tile 2j+1 (frag regs [2],[3])
                mma16816(acc0 + (2 * j + 1) * 4, a0f, b0f + 2);
                mma16816(acc1 + (2 * j + 1) * 4, a0f, b1f + 2);
                mma16816(acc1 + (2 * j + 1) * 4, a1f, b0f + 2);
                mma16816(acc1 + (2 * j + 1) * 4, a1m, b1m + 2);
            }
        }
        if (p + 1 < NCH) __syncthreads();   // stage s reads done before iter p+1
                                            // loads chunk p+2 into stage s
    }

    // ---- epilogue: combine splits, park h in smem (aliases stages) ----
    __syncthreads();
    float* Cs = (float*)smem;               // [128][132]
    const int g  = lid >> 2;
    const int c2 = (lid & 3) * 2;
#pragma unroll
    for (int nt = 0; nt < 16; ++nt) {
        const int col = nt * 8 + c2;
        const float* p0 = acc0 + nt * 4;
        const float* p1 = acc1 + nt * 4;
        float2 v0 = { p0[0] + p1[0] * INV_SCALE, p0[1] + p1[1] * INV_SCALE };
        float2 v1 = { p0[2] + p1[2] * INV_SCALE, p0[3] + p1[3] * INV_SCALE };
        *(float2*)&Cs[(m0 + g) * 132 + col]     = v0;
        *(float2*)&Cs[(m0 + g + 8) * 132 + col] = v1;
    }
    __syncthreads();

    // ---- LIF scan over t; thread = u column (threads 0..127) ----
    if (tid < NT) {
        float* op = out + (size_t)b * T_ * U_ + u0 + tid;
        float syn = 0.f, mem = 0.f;
#pragma unroll 4
        for (int t = 0; t < T_; ++t) {
            const float h = Cs[t * 132 + tid];
            syn = ALPHA_ * syn + h;           // synaptic current decay
            mem = BETA_  * mem + syn;         // membrane decay
            const float spk = (mem - THRESH_ > 0.f) ? 1.f : 0.f;
            mem -= spk * THRESH_;             // soft reset
            op[(size_t)t * U_] = spk;
        }
    }
}

// ---------------- launch ----------------
extern "C" void kernel_launch(void* const* d_in, const int* in_sizes, int n_in,
                              void* d_out, int out_size) {
    (void)in_sizes; (void)n_in; (void)out_size;
    const float* x = (const float*)d_in[0];   // [B, F, T]
    const float* W = (const float*)d_in[1];   // [F, U]
    float* out = (float*)d_out;               // [B, T, U] float32

    cudaFuncSetAttribute(snn_mma_kernel,
                         cudaFuncAttributeMaxDynamicSharedMemorySize, SMEM_TOTAL);

    dim3 gx(KP / 32, T_ / 32, B_);            // 25 x 4 x 256
    split_x_kernel<<<gx, dim3(32, 8)>>>(x);
    dim3 gw(KP / 32, U_ / 32);                // 25 x 64
    split_w_kernel<<<gw, dim3(32, 8)>>>(W);

    dim3 grid(U_ / NT, B_);                   // 16 x 256 = 4096 CTAs
    snn_mma_kernel<<<grid, 256, SMEM_TOTAL>>>(out);
}

// round 11
// speedup vs baseline: 5.6328x; 1.0549x over previous
#include <cuda_runtime.h>
#include <cuda_fp16.h>
#include <cstdint>
#include <cstddef>

// ---------------- problem shape ----------------
#define B_  256
#define F_  784
#define T_  128
#define U_  2048
#define KP  800            // K padded to 25*32
#define KC  64             // k per chunk
#define NCH 13             // ceil(KP/KC): 12 full + last covers [768,800)+zeros? NO:
                           // 13*64 = 832 > 800 -> pad KP to 832 instead
#undef KP
#define KP  832            // K padded to 13*64 (zeros beyond 784 contribute 0)
#define NT  128            // u-tile per CTA

#define ALPHA_  0.9f
#define BETA_   0.85f
#define THRESH_ 1.0f
#define SPLIT_SCALE 2048.0f
#define INV_SCALE (1.0f / 2048.0f)

// smem stage: 4 arrays (A0,A1,B0,B1) of [128 rows][72 halfs] (64 data + 8 pad)
// row stride 144B -> phase 4*row mod 32 words: 8-row ldmatrix groups cover all banks.
#define ROWH    72
#define ARR_B   (128 * ROWH * 2)      // 18432
#define STAGE_B (4 * ARR_B)           // 73728
#define SMEM_TOTAL (2 * STAGE_B)      // 147456 (epilogue Cs 128*132*4=67584 aliases)

// ---------------- scratch (device globals; allocation-free rule) ----------
__device__ __half X0d[B_][T_][KP];    // 54.5 MB  main split of x, K-major
__device__ __half X1d[B_][T_][KP];    // 54.5 MB  residual*2048
__device__ __half W0d[U_][KP];        // 3.4 MB
__device__ __half W1d[U_][KP];        // 3.4 MB

// ---------------- PTX helpers (all baseline sm_80 ISA -> compute_103 OK) ---
__device__ __forceinline__ void cp_async16(uint32_t saddr, const void* g) {
    asm volatile("cp.async.cg.shared.global [%0], [%1], 16;"
                 :: "r"(saddr), "l"(g) : "memory");
}
__device__ __forceinline__ void cp_commit() {
    asm volatile("cp.async.commit_group;" ::: "memory");
}
__device__ __forceinline__ void cp_wait1() {
    asm volatile("cp.async.wait_group 1;" ::: "memory");
}
__device__ __forceinline__ void cp_wait0() {
    asm volatile("cp.async.wait_group 0;" ::: "memory");
}
// plain (non-trans) ldmatrix x4: lane l gets M[l/4][2*(l%4)..+1] per 8x8 mat.
__device__ __forceinline__ void ldsm4(uint32_t* r, uint32_t addr) {
    asm volatile("ldmatrix.sync.aligned.m8n8.x4.shared.b16 {%0,%1,%2,%3}, [%4];"
                 : "=r"(r[0]), "=r"(r[1]), "=r"(r[2]), "=r"(r[3]) : "r"(addr));
}
__device__ __forceinline__ void mma16816(float* c, const uint32_t* a, const uint32_t* b) {
    asm volatile(
        "mma.sync.aligned.m16n8k16.row.col.f32.f16.f16.f32 "
        "{%0,%1,%2,%3}, {%4,%5,%6,%7}, {%8,%9}, {%0,%1,%2,%3};"
        : "+f"(c[0]), "+f"(c[1]), "+f"(c[2]), "+f"(c[3])
        : "r"(a[0]), "r"(a[1]), "r"(a[2]), "r"(a[3]), "r"(b[0]), "r"(b[1]));
}
// packed fp16x2 multiply (exact for power-of-two scales; results stay normal)
__device__ __forceinline__ uint32_t hmul2(uint32_t a, uint32_t s) {
    uint32_t d;
    asm("mul.f16x2 %0, %1, %2;" : "=r"(d) : "r"(a), "r"(s));
    return d;
}
#define SCALE_A_2M5 0x28002800u   // half2(2^-5, 2^-5)
#define SCALE_B_2M6 0x24002400u   // half2(2^-6, 2^-6)
__device__ __forceinline__ uint32_t s2u(const void* p) {
    return (uint32_t)__cvta_generic_to_shared(p);
}

// ---------------- split precompute ----------------
// x[b][f][t] -> X0/X1 [b][t][f] (transpose), exact fp16 2-split, zero-pad f>=784.
// Same per-element math as before (bit-identical outputs); vectorized half2 stores.
__global__ void split_x_kernel(const float* __restrict__ x) {
    __shared__ float tile[32][33];
    const int b  = blockIdx.z;
    const int f0 = blockIdx.x * 32;
    const int t0 = blockIdx.y * 32;
    const int tx = threadIdx.x, ty = threadIdx.y;
    const int tid = ty * 32 + tx;
    for (int i = ty; i < 32; i += 8) {
        const int f = f0 + i;
        float v = 0.f;
        if (f < F_) v = x[((size_t)b * F_ + f) * T_ + t0 + tx];
        tile[i][tx] = v;
    }
    __syncthreads();
    // writer: 512 half2 stores per array; 2 items per thread
    for (int idx = tid; idx < 32 * 16; idx += 256) {
        const int i = idx >> 4;           // t row 0..31
        const int j = idx & 15;           // f pair 0..15
        const int t = t0 + i;
        const int f = f0 + 2 * j;
        const float v0 = tile[2 * j][i];
        const float v1 = tile[2 * j + 1][i];
        const __half h0a = __float2half_rn(v0);
        const __half h1a = __float2half_rn((v0 - __half2float(h0a)) * SPLIT_SCALE);
        const __half h0b = __float2half_rn(v1);
        const __half h1b = __float2half_rn((v1 - __half2float(h0b)) * SPLIT_SCALE);
        *(__half2*)&X0d[b][t][f] = __halves2half2(h0a, h0b);
        *(__half2*)&X1d[b][t][f] = __halves2half2(h1a, h1b);
    }
}
// W[f][u] -> W0/W1 [u][f] (K-major)
__global__ void split_w_kernel(const float* __restrict__ W) {
    __shared__ float tile[32][33];
    const int f0 = blockIdx.x * 32;
    const int u0 = blockIdx.y * 32;
    const int tx = threadIdx.x, ty = threadIdx.y;
    const int tid = ty * 32 + tx;
    for (int i = ty; i < 32; i += 8) {
        const int f = f0 + i;
        float v = 0.f;
        if (f < F_) v = W[(size_t)f * U_ + u0 + tx];
        tile[i][tx] = v;
    }
    __syncthreads();
    for (int idx = tid; idx < 32 * 16; idx += 256) {
        const int i = idx >> 4;           // u row
        const int j = idx & 15;           // f pair
        const int u = u0 + i;
        const int f = f0 + 2 * j;
        const float v0 = tile[2 * j][i];
        const float v1 = tile[2 * j + 1][i];
        const __half h0a = __float2half_rn(v0);
        const __half h1a = __float2half_rn((v0 - __half2float(h0a)) * SPLIT_SCALE);
        const __half h0b = __float2half_rn(v1);
        const __half h1b = __float2half_rn((v1 - __half2float(h0b)) * SPLIT_SCALE);
        *(__half2*)&W0d[u][f] = __halves2half2(h0a, h0b);
        *(__half2*)&W1d[u][f] = __halves2half2(h1a, h1b);
    }
}

// ---------------- chunk loader: 16 cp.async16 per thread ----------------
__device__ __forceinline__ void load_chunk(uint32_t sb, int stage, int p,
                                           int b, int u0, int tid) {
    const uint32_t st = sb + stage * STAGE_B;
    const int k0 = p * KC;
    const __half* src[4] = { &X0d[b][0][k0], &X1d[b][0][k0],
                             &W0d[u0][k0],  &W1d[u0][k0] };
#pragma unroll
    for (int arr = 0; arr < 4; ++arr) {
#pragma unroll
        for (int i = 0; i < 4; ++i) {
            const int u_  = tid + 256 * i;       // 0..1023
            const int row = u_ >> 3;             // 0..127
            const int c16 = u_ & 7;              // 16B unit within 128B row data
            cp_async16(st + arr * ARR_B + row * (ROWH * 2) + c16 * 16,
                       (const char*)src[arr] + (size_t)row * (KP * 2) + c16 * 16);
        }
    }
}

// ---------------- fused mma.sync GEMM + LIF scan ----------------
// Full-precision split product: h = a0b0 + (a0b1 + a1b0 + (a1*2^-5)(b1*2^-6))/2048
// Per-accumulator k16 order is ascending and term order fixed -> bit-identical
// to the R10 kernel (rel_err must match exactly).
__global__ __launch_bounds__(256, 1)
void snn_mma_kernel(float* __restrict__ out)
{
    extern __shared__ __align__(128) char smem[];
    const uint32_t sb = s2u(smem);
    const int tid = threadIdx.x;
    const int wid = tid >> 5;
    const int lid = tid & 31;
    const int u0  = blockIdx.x * NT;
    const int b   = blockIdx.y;
    const int m0  = wid * 16;                 // this warp's t rows

    // accumulators: 16 n-tiles x 4 regs, two sets (main, x2048 correction)
    float acc0[64], acc1[64];
#pragma unroll
    for (int i = 0; i < 64; ++i) { acc0[i] = 0.f; acc1[i] = 0.f; }

    // ldmatrix source addressing (lane-dependent row/col-half)
    const int ar = m0 + (lid & 15);           // A rows m0..m0+15
    const int ac = (lid >> 4) & 1;            // k col-half (0:k0-7, 1:k8-15)
    const int brbase = (lid & 7) + ((lid & 16) ? 8 : 0);   // B row within n-pair
    const int bc = (lid >> 3) & 1;

    load_chunk(sb, 0, 0, b, u0, tid);
    cp_commit();

    for (int p = 0; p < NCH; ++p) {
        const int s = p & 1;
        if (p + 1 < NCH) { load_chunk(sb, s ^ 1, p + 1, b, u0, tid); cp_commit(); }
        if (p + 1 < NCH) cp_wait1(); else cp_wait0();   // chunk p landed (mine)
        __syncthreads();                                 // everyone's landed

        const uint32_t st = sb + s * STAGE_B;
#pragma unroll
        for (int ks = 0; ks < 4; ++ks) {                 // four k16 steps
            uint32_t a0f[4], a1f[4], a1m[4];
            const uint32_t aoff = st + ar * (ROWH * 2) + ks * 32 + ac * 16;
            ldsm4(a0f, aoff);                            // A0
            ldsm4(a1f, aoff + ARR_B);                    // A1 (residual*2048)
#pragma unroll
            for (int i = 0; i < 4; ++i) a1m[i] = hmul2(a1f[i], SCALE_A_2M5);
#pragma unroll
            for (int j = 0; j < 8; ++j) {                // n-pairs (16 u each)
                uint32_t b0f[4], b1f[4], b1m[4];
                const uint32_t boff = st + 2 * ARR_B
                    + (j * 16 + brbase) * (ROWH * 2) + ks * 32 + bc * 16;
                ldsm4(b0f, boff);                        // W0
                ldsm4(b1f, boff + ARR_B);                // W1 (residual*2048)
#pragma unroll
                for (int i = 0; i < 4; ++i) b1m[i] = hmul2(b1f[i], SCALE_B_2M6);
                // n-tile 2j   (frag regs [0],[1])
                mma16816(acc0 + (2 * j) * 4,     a0f, b0f);
                mma16816(acc1 + (2 * j) * 4,     a0f, b1f);
                mma16816(acc1 + (2 * j) * 4,     a1f, b0f);
                mma16816(acc1 + (2 * j) * 4,     a1m, b1m);
                // n-tile 2j+1 (frag regs [2],[3])
                mma16816(acc0 + (2 * j + 1) * 4, a0f, b0f + 2);
                mma16816(acc1 + (2 * j + 1) * 4, a0f, b1f + 2);
                mma16816(acc1 + (2 * j + 1) * 4, a1f, b0f + 2);
                mma16816(acc1 + (2 * j + 1) * 4, a1m, b1m + 2);
            }
        }
        if (p + 1 < NCH) __syncthreads();   // stage s reads done before iter p+1
                                            // loads chunk p+2 into stage s
    }

    // ---- epilogue: combine splits, park h in smem (aliases stages) ----
    __syncthreads();
    float* Cs = (float*)smem;               // [128][132]
    const int g  = lid >> 2;
    const int c2 = (lid & 3) * 2;
#pragma unroll
    for (int nt = 0; nt < 16; ++nt) {
        const int col = nt * 8 + c2;
        const float* p0 = acc0 + nt * 4;
        const float* p1 = acc1 + nt * 4;
        float2 v0 = { p0[0] + p1[0] * INV_SCALE, p0[1] + p1[1] * INV_SCALE };
        float2 v1 = { p0[2] + p1[2] * INV_SCALE, p0[3] + p1[3] * INV_SCALE };
        *(float2*)&Cs[(m0 + g) * 132 + col]     = v0;
        *(float2*)&Cs[(m0 + g + 8) * 132 + col] = v1;
    }
    __syncthreads();

    // ---- LIF scan over t; thread = u column (threads 0..127) ----
    if (tid < NT) {
        float* op = out + (size_t)b * T_ * U_ + u0 + tid;
        float syn = 0.f, mem = 0.f;
#pragma unroll 4
        for (int t = 0; t < T_; ++t) {
            const float h = Cs[t * 132 + tid];
            syn = ALPHA_ * syn + h;           // synaptic current decay
            mem = BETA_  * mem + syn;         // membrane decay
            const float spk = (mem - THRESH_ > 0.f) ? 1.f : 0.f;
            mem -= spk * THRESH_;             // soft reset
            op[(size_t)t * U_] = spk;
        }
    }
}

// ---------------- launch ----------------
extern "C" void kernel_launch(void* const* d_in, const int* in_sizes, int n_in,
                              void* d_out, int out_size) {
    (void)in_sizes; (void)n_in; (void)out_size;
    const float* x = (const float*)d_in[0];   // [B, F, T]
    const float* W = (const float*)d_in[1];   // [F, U]
    float* out = (float*)d_out;               // [B, T, U] float32

    cudaFuncSetAttribute(snn_mma_kernel,
                         cudaFuncAttributeMaxDynamicSharedMemorySize, SMEM_TOTAL);

    dim3 gx(KP / 32, T_ / 32, B_);            // 26 x 4 x 256
    split_x_kernel<<<gx, dim3(32, 8)>>>(x);
    dim3 gw(KP / 32, U_ / 32);                // 26 x 64
    split_w_kernel<<<gw, dim3(32, 8)>>>(W);

    dim3 grid(U_ / NT, B_);                   // 16 x 256 = 4096 CTAs
    snn_mma_kernel<<<grid, 256, SMEM_TOTAL>>>(out);
}